// round 5
// baseline (speedup 1.0000x reference)
#include <cuda_runtime.h>
#include <cuda_fp16.h>
#include <mma.h>
#include <cstdint>
#include <cstddef>

using namespace nvcuda;

// ---------------- problem constants ----------------
#define Dc     1024
#define DFFc   4096
#define Ec     16
#define TKc    4
#define STEPSc 4
#define Tc     2048
#define RMAXc  (Tc*TKc)
#define PEREXP (DFFc*Dc)

// ---------------- device scratch ----------------
__device__ __half g_w1q[(size_t)Ec*DFFc*Dc];
__device__ __half g_w2q[(size_t)Ec*DFFc*Dc];
__device__ float  g_gateq[Ec*Dc];
__device__ float  g_g1[Ec];
__device__ float  g_g2[Ec];
__device__ float  g_part[32*1024];
__device__ float  g_state[Tc*Dc];
__device__ __half g_ctx_hi[Tc*Dc];
__device__ __half g_ctx_lo[Tc*Dc];
__device__ __half g_h_hi[(size_t)RMAXc*DFFc];
__device__ __half g_h_lo[(size_t)RMAXc*DFFc];
__device__ float  g_osl[(size_t)RMAXc*Dc];
__device__ int    g_list[Ec*Tc];
__device__ int    g_sel[Tc*TKc];
__device__ int    g_cnt[Ec];
__device__ int    g_off[Ec];

// ---------------- async-copy helpers (baseline PTX, sm_80+) ----------------
__device__ __forceinline__ uint32_t s2u(const void* p) {
    return (uint32_t)__cvta_generic_to_shared(p);
}
#define CP16(dst, src) \
    asm volatile("cp.async.cg.shared.global [%0], [%1], 16;" \
                 :: "r"(dst), "l"((const void*)(src)) : "memory")
#define CP_COMMIT() asm volatile("cp.async.commit_group;" ::: "memory")
#define CP_WAIT2()  asm volatile("cp.async.wait_group 2;" ::: "memory")

// ---------------- small utility kernels ----------------
__global__ void copy_in_kernel(const float* __restrict__ x) {
    int i = blockIdx.x * blockDim.x + threadIdx.x;
    if (i < Tc*Dc) g_state[i] = x[i];
}
__global__ void copy_out_kernel(float* __restrict__ out) {
    int i = blockIdx.x * blockDim.x + threadIdx.x;
    if (i < Tc*Dc) out[i] = g_state[i];
}
__global__ void zero_cnt_kernel() { if (threadIdx.x < Ec) g_cnt[threadIdx.x] = 0; }

__global__ void offsets_kernel() {
    if (threadIdx.x == 0) {
        int r = 0;
        for (int e = 0; e < Ec; e++) { g_off[e] = r; r += g_cnt[e]; }
    }
}

// ---------------- quantization ----------------
__global__ void abs_partial_kernel(const float* __restrict__ w1, const float* __restrict__ w2) {
    int chunk = blockIdx.x;
    int tn    = blockIdx.y;
    const float* base = (tn < Ec) ? (w1 + (size_t)tn * PEREXP)
                                  : (w2 + (size_t)(tn - Ec) * PEREXP);
    base += (size_t)chunk * 4096;
    int tid = threadIdx.x;
    float s = 0.f;
    #pragma unroll
    for (int i = 0; i < 16; i++) s += fabsf(base[tid + i*256]);
    __shared__ float red[256];
    red[tid] = s; __syncthreads();
    for (int st = 128; st > 0; st >>= 1) { if (tid < st) red[tid] += red[tid+st]; __syncthreads(); }
    if (tid == 0) g_part[tn*1024 + chunk] = red[0];
}

__global__ void scales_kernel() {
    int tn = blockIdx.x;
    int tid = threadIdx.x;
    float s = 0.f;
    for (int i = tid; i < 1024; i += 256) s += g_part[tn*1024 + i];
    __shared__ float red[256];
    red[tid] = s; __syncthreads();
    for (int st = 128; st > 0; st >>= 1) { if (tid < st) red[tid] += red[tid+st]; __syncthreads(); }
    if (tid == 0) {
        float g = fmaxf(red[0] / (float)PEREXP, 1e-5f);
        if (tn < Ec) g_g1[tn] = g; else g_g2[tn - Ec] = g;
    }
}

__global__ void gate_kernel(const float* __restrict__ gw) {
    int tid = threadIdx.x;
    float s = 0.f;
    for (int i = tid; i < Ec*Dc; i += 256) s += fabsf(gw[i]);
    __shared__ float red[256];
    __shared__ float sg;
    red[tid] = s; __syncthreads();
    for (int st = 128; st > 0; st >>= 1) { if (tid < st) red[tid] += red[tid+st]; __syncthreads(); }
    if (tid == 0) sg = fmaxf(red[0] / (float)(Ec*Dc), 1e-5f);
    __syncthreads();
    float g = sg;
    for (int i = tid; i < Ec*Dc; i += 256) {
        float q = rintf(gw[i] / g);
        g_gateq[i] = fminf(fmaxf(q, -1.f), 1.f);
    }
}

__global__ void quantw_kernel(const float* __restrict__ w, int which) {
    __half* q = which ? g_w2q : g_w1q;
    const float* gs = which ? g_g2 : g_g1;
    size_t nvec   = (size_t)Ec * PEREXP / 4;
    size_t stride = (size_t)gridDim.x * blockDim.x;
    for (size_t i = (size_t)blockIdx.x * blockDim.x + threadIdx.x; i < nvec; i += stride) {
        int e = (int)((i * 4) / (size_t)PEREXP);
        float g = gs[e];
        float4 v = reinterpret_cast<const float4*>(w)[i];
        float q0 = fminf(fmaxf(rintf(v.x / g), -1.f), 1.f);
        float q1 = fminf(fmaxf(rintf(v.y / g), -1.f), 1.f);
        float q2 = fminf(fmaxf(rintf(v.z / g), -1.f), 1.f);
        float q3 = fminf(fmaxf(rintf(v.w / g), -1.f), 1.f);
        __half2* qo = reinterpret_cast<__half2*>(q) + i*2;
        qo[0] = __floats2half2_rn(q0, q1);
        qo[1] = __floats2half2_rn(q2, q3);
    }
}

// ---------------- routing ----------------
__global__ void route_kernel(const float* __restrict__ comp, const float* __restrict__ temb, int step) {
    int t = blockIdx.x, tid = threadIdx.x;
    if (!(comp[t] > 0.5f)) {
        #pragma unroll
        for (int i = 0; i < 8; i++) {
            int d = tid + i*128;
            g_ctx_hi[t*Dc + d] = __float2half(0.f);
            g_ctx_lo[t*Dc + d] = __float2half(0.f);
        }
        return;
    }
    float cx[8];
    #pragma unroll
    for (int i = 0; i < 8; i++) {
        int d = tid + i*128;
        float v = g_state[t*Dc + d] + temb[step*Dc + d];
        cx[i] = v;
        __half hi = __float2half(v);
        g_ctx_hi[t*Dc + d] = hi;
        g_ctx_lo[t*Dc + d] = __float2half(v - __half2float(hi));
    }
    float p[16];
    #pragma unroll
    for (int e = 0; e < 16; e++) p[e] = 0.f;
    #pragma unroll
    for (int i = 0; i < 8; i++) {
        int d = tid + i*128;
        #pragma unroll
        for (int e = 0; e < 16; e++) p[e] += cx[i] * g_gateq[e*Dc + d];
    }
    __shared__ float wsum[4][16];
    __shared__ float slog[16];
    int lane = tid & 31, wp = tid >> 5;
    #pragma unroll
    for (int e = 0; e < 16; e++) {
        float s = p[e];
        for (int o = 16; o > 0; o >>= 1) s += __shfl_down_sync(0xffffffffu, s, o);
        if (lane == 0) wsum[wp][e] = s;
    }
    __syncthreads();
    if (tid < 16) slog[tid] = wsum[0][tid] + wsum[1][tid] + wsum[2][tid] + wsum[3][tid];
    __syncthreads();
    if (tid == 0) {
        float lg[16];
        #pragma unroll
        for (int e = 0; e < 16; e++) lg[e] = slog[e];
        for (int k = 0; k < TKc; k++) {
            int best = 0; float bv = lg[0];
            for (int e = 1; e < 16; e++) if (lg[e] > bv) { bv = lg[e]; best = e; }
            g_sel[t*TKc + k] = best;
            lg[best] = -3.4e38f;
            int pos = atomicAdd(&g_cnt[best], 1);
            g_list[best*Tc + pos] = t*TKc + k;
        }
    }
}

// ==================================================================
// wmma GEMM, 128(M) x 128(N) block tile, K-chunk 64, 3-stage cp.async
// 8 warps in 4(M) x 2(N); warp tile 32x64. Split-fp16 A (hi + lo).
// Per stage: AsHi[128][72] + AsLo[128][72] + Bs[128][72] = 54 KB.
// 3 stages = 162 KB dynamic smem. Epilogue reuses stage 0 as fp32 Cs.
// ==================================================================
#define ARR_BYTES   18432            // 128*72*2
#define STAGE_BYTES (3*ARR_BYTES)    // 55296
#define DSM_BYTES   (3*STAGE_BYTES)  // 165888

// ---------------- FFN1: H = gelu(g1 * ctx @ W1^T) ----------------
__global__ void __launch_bounds__(256) ffn1_kernel() {
    extern __shared__ char dsm[];
    __shared__ int rowc[128];

    int e   = blockIdx.z;
    int cnt = g_cnt[e];
    int m0  = blockIdx.x * 128;
    if (m0 >= cnt) return;
    int n0  = blockIdx.y * 128;
    int tid = threadIdx.x;

    if (tid < 128) rowc[tid] = (m0 + tid < cnt) ? g_list[e*Tc + m0 + tid] : -1;
    __syncthreads();

    uint32_t sb = s2u(dsm);
    const __half* W = g_w1q + (size_t)e*DFFc*Dc + (size_t)n0*Dc;

    auto stage = [&](int chunk, int slot) {
        int k0 = chunk << 6;
        uint32_t aHi = sb + (uint32_t)slot * STAGE_BYTES;
        uint32_t aLo = aHi + ARR_BYTES;
        uint32_t bS  = aLo + ARR_BYTES;
        #pragma unroll
        for (int it = 0; it < 4; it++) {
            int u = tid + (it << 8);          // 0..1023
            int r = u >> 3, gi = u & 7;       // row 0..127, 16B-granule 0..7
            uint32_t off = (uint32_t)(r*144 + gi*16);
            int code = rowc[r];
            int tok = code >= 0 ? (code >> 2) : 0;
            CP16(aHi + off, g_ctx_hi + (size_t)tok*Dc + k0 + (gi<<3));
            CP16(aLo + off, g_ctx_lo + (size_t)tok*Dc + k0 + (gi<<3));
            CP16(bS  + off, W + (size_t)r*Dc + k0 + (gi<<3));
        }
    };

    const int KC = Dc / 64;   // 16
    stage(0, 0); CP_COMMIT();
    stage(1, 1); CP_COMMIT();
    stage(2, 2); CP_COMMIT();

    int warp = tid >> 5;
    int wm = warp >> 1, wn = warp & 1;     // 4x2 warp grid, warp tile 32x64
    wmma::fragment<wmma::accumulator,16,16,16,float> acc[2][4];
    #pragma unroll
    for (int i = 0; i < 2; i++)
        #pragma unroll
        for (int j = 0; j < 4; j++) wmma::fill_fragment(acc[i][j], 0.f);

    for (int c = 0; c < KC; c++) {
        CP_WAIT2();
        __syncthreads();
        int slot = c % 3;
        __half* AsHi = (__half*)(dsm + (size_t)slot*STAGE_BYTES);
        __half* AsLo = (__half*)(dsm + (size_t)slot*STAGE_BYTES + ARR_BYTES);
        __half* Bs   = (__half*)(dsm + (size_t)slot*STAGE_BYTES + 2*ARR_BYTES);
        #pragma unroll
        for (int kk = 0; kk < 64; kk += 16) {
            wmma::fragment<wmma::matrix_a,16,16,16,__half,wmma::row_major> aHi[2], aLo[2];
            wmma::fragment<wmma::matrix_b,16,16,16,__half,wmma::col_major> b[4];
            #pragma unroll
            for (int i = 0; i < 2; i++) {
                wmma::load_matrix_sync(aHi[i], AsHi + (size_t)(wm*32 + i*16)*72 + kk, 72);
                wmma::load_matrix_sync(aLo[i], AsLo + (size_t)(wm*32 + i*16)*72 + kk, 72);
            }
            #pragma unroll
            for (int j = 0; j < 4; j++)
                wmma::load_matrix_sync(b[j], Bs + (size_t)(wn*64 + j*16)*72 + kk, 72);
            #pragma unroll
            for (int i = 0; i < 2; i++)
                #pragma unroll
                for (int j = 0; j < 4; j++) {
                    wmma::mma_sync(acc[i][j], aHi[i], b[j], acc[i][j]);
                    wmma::mma_sync(acc[i][j], aLo[i], b[j], acc[i][j]);
                }
        }
        __syncthreads();
        if (c + 3 < KC) stage(c + 3, slot);
        CP_COMMIT();                      // commit every iter (incl. empty) to keep counts exact
    }

    // epilogue via smem (reuse stage memory)
    float* Cs = (float*)dsm;              // [128][132]
    #pragma unroll
    for (int i = 0; i < 2; i++)
        #pragma unroll
        for (int j = 0; j < 4; j++)
            wmma::store_matrix_sync(Cs + (size_t)(wm*32 + i*16)*132 + wn*64 + j*16,
                                    acc[i][j], 132, wmma::mem_row_major);
    __syncthreads();

    float g1 = g_g1[e];
    int off  = g_off[e];
    for (int idx = tid; idx < 128*64; idx += 256) {
        int r = idx >> 6, cp = (idx & 63) << 1;
        if (rowc[r] < 0) continue;
        float v0 = g1 * Cs[(size_t)r*132 + cp];
        float v1 = g1 * Cs[(size_t)r*132 + cp + 1];
        float e0 = 0.5f * v0 * (1.0f + erff(v0 * 0.7071067811865476f));
        float e1 = 0.5f * v1 * (1.0f + erff(v1 * 0.7071067811865476f));
        __half h0 = __float2half(e0), h1 = __float2half(e1);
        size_t o = (size_t)(off + m0 + r)*DFFc + n0 + cp;
        *reinterpret_cast<__half2*>(&g_h_hi[o]) = __halves2half2(h0, h1);
        *reinterpret_cast<__half2*>(&g_h_lo[o]) =
            __halves2half2(__float2half(e0 - __half2float(h0)),
                           __float2half(e1 - __half2float(h1)));
    }
}

// ---------------- FFN2: O = g2 * H @ W2^T ----------------
__global__ void __launch_bounds__(256) ffn2_kernel() {
    extern __shared__ char dsm[];
    __shared__ int rowc[128];

    int e   = blockIdx.z;
    int cnt = g_cnt[e];
    int m0  = blockIdx.x * 128;
    if (m0 >= cnt) return;
    int n0  = blockIdx.y * 128;
    int tid = threadIdx.x;
    int off = g_off[e];

    if (tid < 128) rowc[tid] = (m0 + tid < cnt) ? g_list[e*Tc + m0 + tid] : -1;
    __syncthreads();

    uint32_t sb = s2u(dsm);
    const __half* W = g_w2q + (size_t)e*DFFc*Dc + (size_t)n0*DFFc;
    int lastrow = off + cnt - 1;

    auto stage = [&](int chunk, int slot) {
        int k0 = chunk << 6;
        uint32_t aHi = sb + (uint32_t)slot * STAGE_BYTES;
        uint32_t aLo = aHi + ARR_BYTES;
        uint32_t bS  = aLo + ARR_BYTES;
        #pragma unroll
        for (int it = 0; it < 4; it++) {
            int u = tid + (it << 8);
            int r = u >> 3, gi = u & 7;
            uint32_t off2 = (uint32_t)(r*144 + gi*16);
            int src = off + m0 + r; if (src > lastrow) src = lastrow;
            CP16(aHi + off2, g_h_hi + (size_t)src*DFFc + k0 + (gi<<3));
            CP16(aLo + off2, g_h_lo + (size_t)src*DFFc + k0 + (gi<<3));
            CP16(bS  + off2, W + (size_t)r*DFFc + k0 + (gi<<3));
        }
    };

    const int KC = DFFc / 64;   // 64
    stage(0, 0); CP_COMMIT();
    stage(1, 1); CP_COMMIT();
    stage(2, 2); CP_COMMIT();

    int warp = tid >> 5;
    int wm = warp >> 1, wn = warp & 1;
    wmma::fragment<wmma::accumulator,16,16,16,float> acc[2][4];
    #pragma unroll
    for (int i = 0; i < 2; i++)
        #pragma unroll
        for (int j = 0; j < 4; j++) wmma::fill_fragment(acc[i][j], 0.f);

    for (int c = 0; c < KC; c++) {
        CP_WAIT2();
        __syncthreads();
        int slot = c % 3;
        __half* AsHi = (__half*)(dsm + (size_t)slot*STAGE_BYTES);
        __half* AsLo = (__half*)(dsm + (size_t)slot*STAGE_BYTES + ARR_BYTES);
        __half* Bs   = (__half*)(dsm + (size_t)slot*STAGE_BYTES + 2*ARR_BYTES);
        #pragma unroll
        for (int kk = 0; kk < 64; kk += 16) {
            wmma::fragment<wmma::matrix_a,16,16,16,__half,wmma::row_major> aHi[2], aLo[2];
            wmma::fragment<wmma::matrix_b,16,16,16,__half,wmma::col_major> b[4];
            #pragma unroll
            for (int i = 0; i < 2; i++) {
                wmma::load_matrix_sync(aHi[i], AsHi + (size_t)(wm*32 + i*16)*72 + kk, 72);
                wmma::load_matrix_sync(aLo[i], AsLo + (size_t)(wm*32 + i*16)*72 + kk, 72);
            }
            #pragma unroll
            for (int j = 0; j < 4; j++)
                wmma::load_matrix_sync(b[j], Bs + (size_t)(wn*64 + j*16)*72 + kk, 72);
            #pragma unroll
            for (int i = 0; i < 2; i++)
                #pragma unroll
                for (int j = 0; j < 4; j++) {
                    wmma::mma_sync(acc[i][j], aHi[i], b[j], acc[i][j]);
                    wmma::mma_sync(acc[i][j], aLo[i], b[j], acc[i][j]);
                }
        }
        __syncthreads();
        if (c + 3 < KC) stage(c + 3, slot);
        CP_COMMIT();
    }

    float* Cs = (float*)dsm;
    #pragma unroll
    for (int i = 0; i < 2; i++)
        #pragma unroll
        for (int j = 0; j < 4; j++)
            wmma::store_matrix_sync(Cs + (size_t)(wm*32 + i*16)*132 + wn*64 + j*16,
                                    acc[i][j], 132, wmma::mem_row_major);
    __syncthreads();

    float g2 = g_g2[e];
    for (int idx = tid; idx < 128*128; idx += 256) {
        int r = idx >> 7, c2 = idx & 127;
        int sc = rowc[r];
        if (sc < 0) continue;
        g_osl[(size_t)sc*Dc + n0 + c2] = g2 * Cs[(size_t)r*132 + c2];
    }
}

// ---------------- combine ----------------
__global__ void combine_kernel(const float* __restrict__ comp, const float* __restrict__ normw) {
    int t = blockIdx.x, tid = threadIdx.x;
    if (!(comp[t] > 0.5f)) return;
    int se[4];
    #pragma unroll
    for (int k = 0; k < 4; k++) se[k] = g_sel[t*4 + k];
    int ord[4] = {0,1,2,3};
    #pragma unroll
    for (int a = 0; a < 3; a++)
        #pragma unroll
        for (int b = a+1; b < 4; b++)
            if (se[ord[b]] < se[ord[a]]) { int tmp = ord[a]; ord[a] = ord[b]; ord[b] = tmp; }
    float y[4]; float ss = 0.f;
    #pragma unroll
    for (int i = 0; i < 4; i++) {
        int d = tid + i*256;
        float s = g_osl[(size_t)(t*4 + ord[0])*Dc + d];
        s += g_osl[(size_t)(t*4 + ord[1])*Dc + d];
        s += g_osl[(size_t)(t*4 + ord[2])*Dc + d];
        s += g_osl[(size_t)(t*4 + ord[3])*Dc + d];
        float v = s + g_state[t*Dc + d];
        y[i] = v; ss += v*v;
    }
    int lane = tid & 31, wp = tid >> 5;
    for (int o = 16; o > 0; o >>= 1) ss += __shfl_down_sync(0xffffffffu, ss, o);
    __shared__ float ws[8];
    __shared__ float svar;
    if (lane == 0) ws[wp] = ss;
    __syncthreads();
    if (tid == 0) {
        float s2 = 0.f;
        for (int w = 0; w < 8; w++) s2 += ws[w];
        svar = s2 * (1.f / (float)Dc);
    }
    __syncthreads();
    float rinv = rsqrtf(svar + 1e-6f);
    #pragma unroll
    for (int i = 0; i < 4; i++) {
        int d = tid + i*256;
        g_state[t*Dc + d] = normw[d] * y[i] * rinv;
    }
}

// ---------------- launch ----------------
extern "C" void kernel_launch(void* const* d_in, const int* in_sizes, int n_in,
                              void* d_out, int out_size) {
    const float* x    = (const float*)d_in[0];
    const float* comp = (const float*)d_in[1];
    const float* gw   = (const float*)d_in[2];
    const float* w1   = (const float*)d_in[3];
    const float* w2   = (const float*)d_in[4];
    const float* temb = (const float*)d_in[5];
    const float* nw   = (const float*)d_in[6];
    float* out = (float*)d_out;

    cudaFuncSetAttribute(ffn1_kernel, cudaFuncAttributeMaxDynamicSharedMemorySize, DSM_BYTES);
    cudaFuncSetAttribute(ffn2_kernel, cudaFuncAttributeMaxDynamicSharedMemorySize, DSM_BYTES);

    copy_in_kernel<<<(Tc*Dc + 511)/512, 512>>>(x);

    abs_partial_kernel<<<dim3(1024, 32), 256>>>(w1, w2);
    scales_kernel<<<32, 256>>>();
    gate_kernel<<<1, 256>>>(gw);
    quantw_kernel<<<8192, 256>>>(w1, 0);
    quantw_kernel<<<8192, 256>>>(w2, 1);

    for (int s = 0; s < STEPSc; s++) {
        zero_cnt_kernel<<<1, 32>>>();
        route_kernel<<<Tc, 128>>>(comp, temb, s);
        offsets_kernel<<<1, 32>>>();
        ffn1_kernel<<<dim3(Tc/128, DFFc/128, Ec), 256, DSM_BYTES>>>();
        ffn2_kernel<<<dim3(Tc/128, Dc/128, Ec), 256, DSM_BYTES>>>();
        combine_kernel<<<Tc, 256>>>(comp, nw);
    }

    copy_out_kernel<<<(Tc*Dc + 511)/512, 512>>>(out);
}

// round 6
// speedup vs baseline: 1.3087x; 1.3087x over previous
#include <cuda_runtime.h>
#include <cuda_fp16.h>
#include <mma.h>
#include <cstdint>
#include <cstddef>

using namespace nvcuda;

// ---------------- problem constants ----------------
#define Dc     1024
#define DFFc   4096
#define Ec     16
#define TKc    4
#define STEPSc 4
#define Tc     2048
#define RMAXc  (Tc*TKc)
#define PEREXP (DFFc*Dc)

// ---------------- device scratch ----------------
__device__ __half g_w1q[(size_t)Ec*DFFc*Dc];
__device__ __half g_w2q[(size_t)Ec*DFFc*Dc];
__device__ float  g_gateq[Ec*Dc];
__device__ float  g_g1[Ec];
__device__ float  g_g2[Ec];
__device__ float  g_part[32*1024];
__device__ float  g_state[Tc*Dc];
__device__ __half g_ctx_hi[Tc*Dc];
__device__ __half g_ctx_lo[Tc*Dc];
__device__ __half g_h_hi[(size_t)RMAXc*DFFc];
__device__ __half g_h_lo[(size_t)RMAXc*DFFc];
__device__ float  g_osl[(size_t)RMAXc*Dc];
__device__ int    g_list[Ec*Tc];
__device__ int    g_sel[Tc*TKc];
__device__ int    g_cnt[Ec];
__device__ int    g_off[Ec];

// ---------------- async-copy helpers ----------------
__device__ __forceinline__ uint32_t s2u(const void* p) {
    return (uint32_t)__cvta_generic_to_shared(p);
}
#define CP16(dst, src) \
    asm volatile("cp.async.cg.shared.global [%0], [%1], 16;" \
                 :: "r"(dst), "l"((const void*)(src)) : "memory")
#define CP_COMMIT() asm volatile("cp.async.commit_group;" ::: "memory")
#define CP_WAIT2()  asm volatile("cp.async.wait_group 2;" ::: "memory")

// ---------------- small utility kernels ----------------
__global__ void copy_in_kernel(const float* __restrict__ x) {
    int i = blockIdx.x * blockDim.x + threadIdx.x;
    if (i < Tc*Dc) g_state[i] = x[i];
}
__global__ void copy_out_kernel(float* __restrict__ out) {
    int i = blockIdx.x * blockDim.x + threadIdx.x;
    if (i < Tc*Dc) out[i] = g_state[i];
}
__global__ void zero_cnt_kernel() { if (threadIdx.x < Ec) g_cnt[threadIdx.x] = 0; }

__global__ void offsets_kernel() {
    if (threadIdx.x == 0) {
        int r = 0;
        for (int e = 0; e < Ec; e++) { g_off[e] = r; r += g_cnt[e]; }
    }
}

// ---------------- quantization ----------------
__global__ void abs_partial_kernel(const float* __restrict__ w1, const float* __restrict__ w2) {
    int chunk = blockIdx.x;
    int tn    = blockIdx.y;
    const float* base = (tn < Ec) ? (w1 + (size_t)tn * PEREXP)
                                  : (w2 + (size_t)(tn - Ec) * PEREXP);
    base += (size_t)chunk * 4096;
    int tid = threadIdx.x;
    float s = 0.f;
    #pragma unroll
    for (int i = 0; i < 16; i++) s += fabsf(base[tid + i*256]);
    __shared__ float red[256];
    red[tid] = s; __syncthreads();
    for (int st = 128; st > 0; st >>= 1) { if (tid < st) red[tid] += red[tid+st]; __syncthreads(); }
    if (tid == 0) g_part[tn*1024 + chunk] = red[0];
}

__global__ void scales_kernel() {
    int tn = blockIdx.x;
    int tid = threadIdx.x;
    float s = 0.f;
    for (int i = tid; i < 1024; i += 256) s += g_part[tn*1024 + i];
    __shared__ float red[256];
    red[tid] = s; __syncthreads();
    for (int st = 128; st > 0; st >>= 1) { if (tid < st) red[tid] += red[tid+st]; __syncthreads(); }
    if (tid == 0) {
        float g = fmaxf(red[0] / (float)PEREXP, 1e-5f);
        if (tn < Ec) g_g1[tn] = g; else g_g2[tn - Ec] = g;
    }
}

__global__ void gate_kernel(const float* __restrict__ gw) {
    int tid = threadIdx.x;
    float s = 0.f;
    for (int i = tid; i < Ec*Dc; i += 256) s += fabsf(gw[i]);
    __shared__ float red[256];
    __shared__ float sg;
    red[tid] = s; __syncthreads();
    for (int st = 128; st > 0; st >>= 1) { if (tid < st) red[tid] += red[tid+st]; __syncthreads(); }
    if (tid == 0) sg = fmaxf(red[0] / (float)(Ec*Dc), 1e-5f);
    __syncthreads();
    float g = sg;
    for (int i = tid; i < Ec*Dc; i += 256) {
        float q = rintf(gw[i] / g);
        g_gateq[i] = fminf(fmaxf(q, -1.f), 1.f);
    }
}

__global__ void quantw_kernel(const float* __restrict__ w, int which) {
    __half* q = which ? g_w2q : g_w1q;
    const float* gs = which ? g_g2 : g_g1;
    size_t nvec   = (size_t)Ec * PEREXP / 4;
    size_t stride = (size_t)gridDim.x * blockDim.x;
    for (size_t i = (size_t)blockIdx.x * blockDim.x + threadIdx.x; i < nvec; i += stride) {
        int e = (int)((i * 4) / (size_t)PEREXP);
        float g = gs[e];
        float4 v = reinterpret_cast<const float4*>(w)[i];
        float q0 = fminf(fmaxf(rintf(v.x / g), -1.f), 1.f);
        float q1 = fminf(fmaxf(rintf(v.y / g), -1.f), 1.f);
        float q2 = fminf(fmaxf(rintf(v.z / g), -1.f), 1.f);
        float q3 = fminf(fmaxf(rintf(v.w / g), -1.f), 1.f);
        __half2* qo = reinterpret_cast<__half2*>(q) + i*2;
        qo[0] = __floats2half2_rn(q0, q1);
        qo[1] = __floats2half2_rn(q2, q3);
    }
}

// ---------------- routing ----------------
__global__ void route_kernel(const float* __restrict__ comp, const float* __restrict__ temb, int step) {
    int t = blockIdx.x, tid = threadIdx.x;
    if (!(comp[t] > 0.5f)) {
        #pragma unroll
        for (int i = 0; i < 8; i++) {
            int d = tid + i*128;
            g_ctx_hi[t*Dc + d] = __float2half(0.f);
            g_ctx_lo[t*Dc + d] = __float2half(0.f);
        }
        return;
    }
    float cx[8];
    #pragma unroll
    for (int i = 0; i < 8; i++) {
        int d = tid + i*128;
        float v = g_state[t*Dc + d] + temb[step*Dc + d];
        cx[i] = v;
        __half hi = __float2half(v);
        g_ctx_hi[t*Dc + d] = hi;
        g_ctx_lo[t*Dc + d] = __float2half(v - __half2float(hi));
    }
    float p[16];
    #pragma unroll
    for (int e = 0; e < 16; e++) p[e] = 0.f;
    #pragma unroll
    for (int i = 0; i < 8; i++) {
        int d = tid + i*128;
        #pragma unroll
        for (int e = 0; e < 16; e++) p[e] += cx[i] * g_gateq[e*Dc + d];
    }
    __shared__ float wsum[4][16];
    __shared__ float slog[16];
    int lane = tid & 31, wp = tid >> 5;
    #pragma unroll
    for (int e = 0; e < 16; e++) {
        float s = p[e];
        for (int o = 16; o > 0; o >>= 1) s += __shfl_down_sync(0xffffffffu, s, o);
        if (lane == 0) wsum[wp][e] = s;
    }
    __syncthreads();
    if (tid < 16) slog[tid] = wsum[0][tid] + wsum[1][tid] + wsum[2][tid] + wsum[3][tid];
    __syncthreads();
    if (tid == 0) {
        float lg[16];
        #pragma unroll
        for (int e = 0; e < 16; e++) lg[e] = slog[e];
        for (int k = 0; k < TKc; k++) {
            int best = 0; float bv = lg[0];
            for (int e = 1; e < 16; e++) if (lg[e] > bv) { bv = lg[e]; best = e; }
            g_sel[t*TKc + k] = best;
            lg[best] = -3.4e38f;
            int pos = atomicAdd(&g_cnt[best], 1);
            g_list[best*Tc + pos] = t*TKc + k;
        }
    }
}

// ==================================================================
// wmma GEMM, 64(M) x 128(N) block tile, K-chunk 64, 3-stage cp.async
// 8 warps in 2(M) x 4(N); warp tile 32x32. Split-fp16 A (hi + lo).
// Per stage: AsHi[64][72] + AsLo[64][72] + Bs[128][72] = 36 KB.
// 3 stages = 108 KB -> 2 CTAs/SM. Epilogue reuses stage memory as Cs.
// ==================================================================
#define A_BYTES     9216             // 64*72*2
#define B_BYTES     18432            // 128*72*2
#define STAGE_BYTES (2*A_BYTES + B_BYTES)   // 36864
#define DSM_BYTES   (3*STAGE_BYTES)         // 110592

// ---------------- FFN1: H = gelu(g1 * ctx @ W1^T) ----------------
__global__ void __launch_bounds__(256) ffn1_kernel() {
    extern __shared__ char dsm[];
    __shared__ int rowc[64];

    int e   = blockIdx.z;
    int cnt = g_cnt[e];
    int m0  = blockIdx.x * 64;
    if (m0 >= cnt) return;
    int n0  = blockIdx.y * 128;
    int tid = threadIdx.x;

    if (tid < 64) rowc[tid] = (m0 + tid < cnt) ? g_list[e*Tc + m0 + tid] : -1;
    __syncthreads();

    uint32_t sb = s2u(dsm);
    const __half* W = g_w1q + (size_t)e*DFFc*Dc + (size_t)n0*Dc;

    auto stage = [&](int chunk, int slot) {
        int k0 = chunk << 6;
        uint32_t aHi = sb + (uint32_t)slot * STAGE_BYTES;
        uint32_t aLo = aHi + A_BYTES;
        uint32_t bS  = aLo + A_BYTES;
        #pragma unroll
        for (int it = 0; it < 2; it++) {          // A tiles: 64x64 halves = 512 uint4
            int u = tid + (it << 8);
            int r = u >> 3, gi = u & 7;
            uint32_t off = (uint32_t)(r*144 + gi*16);
            int code = rowc[r];
            int tok = code >= 0 ? (code >> 2) : 0;
            CP16(aHi + off, g_ctx_hi + (size_t)tok*Dc + k0 + (gi<<3));
            CP16(aLo + off, g_ctx_lo + (size_t)tok*Dc + k0 + (gi<<3));
        }
        #pragma unroll
        for (int it = 0; it < 4; it++) {          // B tile: 128x64 halves = 1024 uint4
            int u = tid + (it << 8);
            int r = u >> 3, gi = u & 7;
            uint32_t off = (uint32_t)(r*144 + gi*16);
            CP16(bS + off, W + (size_t)r*Dc + k0 + (gi<<3));
        }
    };

    const int KC = Dc / 64;   // 16
    stage(0, 0); CP_COMMIT();
    stage(1, 1); CP_COMMIT();
    stage(2, 2); CP_COMMIT();

    int warp = tid >> 5;
    int wm = warp & 1, wn = warp >> 1;     // 2x4 warp grid, warp tile 32x32
    wmma::fragment<wmma::accumulator,16,16,16,float> acc[2][2];
    #pragma unroll
    for (int i = 0; i < 2; i++)
        #pragma unroll
        for (int j = 0; j < 2; j++) wmma::fill_fragment(acc[i][j], 0.f);

    for (int c = 0; c < KC; c++) {
        CP_WAIT2();
        __syncthreads();
        int slot = c % 3;
        __half* AsHi = (__half*)(dsm + (size_t)slot*STAGE_BYTES);
        __half* AsLo = (__half*)(dsm + (size_t)slot*STAGE_BYTES + A_BYTES);
        __half* Bs   = (__half*)(dsm + (size_t)slot*STAGE_BYTES + 2*A_BYTES);
        #pragma unroll
        for (int kk = 0; kk < 64; kk += 16) {
            wmma::fragment<wmma::matrix_a,16,16,16,__half,wmma::row_major> aHi[2], aLo[2];
            wmma::fragment<wmma::matrix_b,16,16,16,__half,wmma::col_major> b[2];
            #pragma unroll
            for (int i = 0; i < 2; i++) {
                wmma::load_matrix_sync(aHi[i], AsHi + (size_t)(wm*32 + i*16)*72 + kk, 72);
                wmma::load_matrix_sync(aLo[i], AsLo + (size_t)(wm*32 + i*16)*72 + kk, 72);
            }
            #pragma unroll
            for (int j = 0; j < 2; j++)
                wmma::load_matrix_sync(b[j], Bs + (size_t)(wn*32 + j*16)*72 + kk, 72);
            #pragma unroll
            for (int i = 0; i < 2; i++)
                #pragma unroll
                for (int j = 0; j < 2; j++) {
                    wmma::mma_sync(acc[i][j], aHi[i], b[j], acc[i][j]);
                    wmma::mma_sync(acc[i][j], aLo[i], b[j], acc[i][j]);
                }
        }
        __syncthreads();
        if (c + 3 < KC) stage(c + 3, slot);
        CP_COMMIT();                      // commit every iter to keep group counts exact
    }

    // epilogue via smem (reuse stage memory): Cs[64][132]
    float* Cs = (float*)dsm;
    #pragma unroll
    for (int i = 0; i < 2; i++)
        #pragma unroll
        for (int j = 0; j < 2; j++)
            wmma::store_matrix_sync(Cs + (size_t)(wm*32 + i*16)*132 + wn*32 + j*16,
                                    acc[i][j], 132, wmma::mem_row_major);
    __syncthreads();

    float g1 = g_g1[e];
    int off  = g_off[e];
    for (int idx = tid; idx < 64*64; idx += 256) {
        int r = idx >> 6, cp = (idx & 63) << 1;
        if (rowc[r] < 0) continue;
        float v0 = g1 * Cs[(size_t)r*132 + cp];
        float v1 = g1 * Cs[(size_t)r*132 + cp + 1];
        float e0 = 0.5f * v0 * (1.0f + erff(v0 * 0.7071067811865476f));
        float e1 = 0.5f * v1 * (1.0f + erff(v1 * 0.7071067811865476f));
        __half h0 = __float2half(e0), h1 = __float2half(e1);
        size_t o = (size_t)(off + m0 + r)*DFFc + n0 + cp;
        *reinterpret_cast<__half2*>(&g_h_hi[o]) = __halves2half2(h0, h1);
        *reinterpret_cast<__half2*>(&g_h_lo[o]) =
            __halves2half2(__float2half(e0 - __half2float(h0)),
                           __float2half(e1 - __half2float(h1)));
    }
}

// ---------------- FFN2: O = g2 * H @ W2^T ----------------
__global__ void __launch_bounds__(256) ffn2_kernel() {
    extern __shared__ char dsm[];
    __shared__ int rowc[64];

    int e   = blockIdx.z;
    int cnt = g_cnt[e];
    int m0  = blockIdx.x * 64;
    if (m0 >= cnt) return;
    int n0  = blockIdx.y * 128;
    int tid = threadIdx.x;
    int off = g_off[e];

    if (tid < 64) rowc[tid] = (m0 + tid < cnt) ? g_list[e*Tc + m0 + tid] : -1;
    __syncthreads();

    uint32_t sb = s2u(dsm);
    const __half* W = g_w2q + (size_t)e*DFFc*Dc + (size_t)n0*DFFc;
    int lastrow = off + cnt - 1;

    auto stage = [&](int chunk, int slot) {
        int k0 = chunk << 6;
        uint32_t aHi = sb + (uint32_t)slot * STAGE_BYTES;
        uint32_t aLo = aHi + A_BYTES;
        uint32_t bS  = aLo + A_BYTES;
        #pragma unroll
        for (int it = 0; it < 2; it++) {
            int u = tid + (it << 8);
            int r = u >> 3, gi = u & 7;
            uint32_t off2 = (uint32_t)(r*144 + gi*16);
            int src = off + m0 + r; if (src > lastrow) src = lastrow;
            CP16(aHi + off2, g_h_hi + (size_t)src*DFFc + k0 + (gi<<3));
            CP16(aLo + off2, g_h_lo + (size_t)src*DFFc + k0 + (gi<<3));
        }
        #pragma unroll
        for (int it = 0; it < 4; it++) {
            int u = tid + (it << 8);
            int r = u >> 3, gi = u & 7;
            uint32_t off2 = (uint32_t)(r*144 + gi*16);
            CP16(bS + off2, W + (size_t)r*DFFc + k0 + (gi<<3));
        }
    };

    const int KC = DFFc / 64;   // 64
    stage(0, 0); CP_COMMIT();
    stage(1, 1); CP_COMMIT();
    stage(2, 2); CP_COMMIT();

    int warp = tid >> 5;
    int wm = warp & 1, wn = warp >> 1;
    wmma::fragment<wmma::accumulator,16,16,16,float> acc[2][2];
    #pragma unroll
    for (int i = 0; i < 2; i++)
        #pragma unroll
        for (int j = 0; j < 2; j++) wmma::fill_fragment(acc[i][j], 0.f);

    for (int c = 0; c < KC; c++) {
        CP_WAIT2();
        __syncthreads();
        int slot = c % 3;
        __half* AsHi = (__half*)(dsm + (size_t)slot*STAGE_BYTES);
        __half* AsLo = (__half*)(dsm + (size_t)slot*STAGE_BYTES + A_BYTES);
        __half* Bs   = (__half*)(dsm + (size_t)slot*STAGE_BYTES + 2*A_BYTES);
        #pragma unroll
        for (int kk = 0; kk < 64; kk += 16) {
            wmma::fragment<wmma::matrix_a,16,16,16,__half,wmma::row_major> aHi[2], aLo[2];
            wmma::fragment<wmma::matrix_b,16,16,16,__half,wmma::col_major> b[2];
            #pragma unroll
            for (int i = 0; i < 2; i++) {
                wmma::load_matrix_sync(aHi[i], AsHi + (size_t)(wm*32 + i*16)*72 + kk, 72);
                wmma::load_matrix_sync(aLo[i], AsLo + (size_t)(wm*32 + i*16)*72 + kk, 72);
            }
            #pragma unroll
            for (int j = 0; j < 2; j++)
                wmma::load_matrix_sync(b[j], Bs + (size_t)(wn*32 + j*16)*72 + kk, 72);
            #pragma unroll
            for (int i = 0; i < 2; i++)
                #pragma unroll
                for (int j = 0; j < 2; j++) {
                    wmma::mma_sync(acc[i][j], aHi[i], b[j], acc[i][j]);
                    wmma::mma_sync(acc[i][j], aLo[i], b[j], acc[i][j]);
                }
        }
        __syncthreads();
        if (c + 3 < KC) stage(c + 3, slot);
        CP_COMMIT();
    }

    float* Cs = (float*)dsm;
    #pragma unroll
    for (int i = 0; i < 2; i++)
        #pragma unroll
        for (int j = 0; j < 2; j++)
            wmma::store_matrix_sync(Cs + (size_t)(wm*32 + i*16)*132 + wn*32 + j*16,
                                    acc[i][j], 132, wmma::mem_row_major);
    __syncthreads();

    float g2 = g_g2[e];
    for (int idx = tid; idx < 64*128; idx += 256) {
        int r = idx >> 7, c2 = idx & 127;
        int sc = rowc[r];
        if (sc < 0) continue;
        g_osl[(size_t)sc*Dc + n0 + c2] = g2 * Cs[(size_t)r*132 + c2];
    }
}

// ---------------- combine ----------------
__global__ void combine_kernel(const float* __restrict__ comp, const float* __restrict__ normw) {
    int t = blockIdx.x, tid = threadIdx.x;
    if (!(comp[t] > 0.5f)) return;
    int se[4];
    #pragma unroll
    for (int k = 0; k < 4; k++) se[k] = g_sel[t*4 + k];
    int ord[4] = {0,1,2,3};
    #pragma unroll
    for (int a = 0; a < 3; a++)
        #pragma unroll
        for (int b = a+1; b < 4; b++)
            if (se[ord[b]] < se[ord[a]]) { int tmp = ord[a]; ord[a] = ord[b]; ord[b] = tmp; }
    float y[4]; float ss = 0.f;
    #pragma unroll
    for (int i = 0; i < 4; i++) {
        int d = tid + i*256;
        float s = g_osl[(size_t)(t*4 + ord[0])*Dc + d];
        s += g_osl[(size_t)(t*4 + ord[1])*Dc + d];
        s += g_osl[(size_t)(t*4 + ord[2])*Dc + d];
        s += g_osl[(size_t)(t*4 + ord[3])*Dc + d];
        float v = s + g_state[t*Dc + d];
        y[i] = v; ss += v*v;
    }
    int lane = tid & 31, wp = tid >> 5;
    for (int o = 16; o > 0; o >>= 1) ss += __shfl_down_sync(0xffffffffu, ss, o);
    __shared__ float ws[8];
    __shared__ float svar;
    if (lane == 0) ws[wp] = ss;
    __syncthreads();
    if (tid == 0) {
        float s2 = 0.f;
        for (int w = 0; w < 8; w++) s2 += ws[w];
        svar = s2 * (1.f / (float)Dc);
    }
    __syncthreads();
    float rinv = rsqrtf(svar + 1e-6f);
    #pragma unroll
    for (int i = 0; i < 4; i++) {
        int d = tid + i*256;
        g_state[t*Dc + d] = normw[d] * y[i] * rinv;
    }
}

// ---------------- launch ----------------
extern "C" void kernel_launch(void* const* d_in, const int* in_sizes, int n_in,
                              void* d_out, int out_size) {
    const float* x    = (const float*)d_in[0];
    const float* comp = (const float*)d_in[1];
    const float* gw   = (const float*)d_in[2];
    const float* w1   = (const float*)d_in[3];
    const float* w2   = (const float*)d_in[4];
    const float* temb = (const float*)d_in[5];
    const float* nw   = (const float*)d_in[6];
    float* out = (float*)d_out;

    cudaFuncSetAttribute(ffn1_kernel, cudaFuncAttributeMaxDynamicSharedMemorySize, DSM_BYTES);
    cudaFuncSetAttribute(ffn2_kernel, cudaFuncAttributeMaxDynamicSharedMemorySize, DSM_BYTES);

    copy_in_kernel<<<(Tc*Dc + 511)/512, 512>>>(x);

    abs_partial_kernel<<<dim3(1024, 32), 256>>>(w1, w2);
    scales_kernel<<<32, 256>>>();
    gate_kernel<<<1, 256>>>(gw);
    quantw_kernel<<<8192, 256>>>(w1, 0);
    quantw_kernel<<<8192, 256>>>(w2, 1);

    for (int s = 0; s < STEPSc; s++) {
        zero_cnt_kernel<<<1, 32>>>();
        route_kernel<<<Tc, 128>>>(comp, temb, s);
        offsets_kernel<<<1, 32>>>();
        ffn1_kernel<<<dim3(Tc/64, DFFc/128, Ec), 256, DSM_BYTES>>>();
        ffn2_kernel<<<dim3(Tc/64, Dc/128, Ec), 256, DSM_BYTES>>>();
        combine_kernel<<<Tc, 256>>>(comp, nw);
    }

    copy_out_kernel<<<(Tc*Dc + 511)/512, 512>>>(out);
}